// round 7
// baseline (speedup 1.0000x reference)
#include <cuda_runtime.h>

#define TPB 128
#define ROWS_PER_BLOCK (2 * TPB)
#define NSTEP 7

typedef unsigned long long u64;

// ---------- f32x2 packed helpers ----------
__device__ __forceinline__ u64 pk(float lo, float hi) {
    u64 d; asm("mov.b64 %0, {%1, %2};" : "=l"(d) : "f"(lo), "f"(hi)); return d;
}
__device__ __forceinline__ void unpk(u64 d, float& lo, float& hi) {
    asm("mov.b64 {%0, %1}, %2;" : "=f"(lo), "=f"(hi) : "l"(d));
}
__device__ __forceinline__ u64 fma2_(u64 a, u64 b, u64 c) {
    u64 d; asm("fma.rn.f32x2 %0, %1, %2, %3;" : "=l"(d) : "l"(a), "l"(b), "l"(c)); return d;
}
__device__ __forceinline__ u64 add2_(u64 a, u64 b) {
    u64 d; asm("add.rn.f32x2 %0, %1, %2;" : "=l"(d) : "l"(a), "l"(b)); return d;
}
__device__ __forceinline__ float ftanh(float x) {
    float y; asm("tanh.approx.f32 %0, %1;" : "=f"(y) : "f"(x)); return y;
}

// One GRU cell, hidden=2. Gates split into x-only chains (off the h critical
// path; ptxas hoists them into the previous cell's tanh latency) seeded into
// 2-deep h-chains.
// W layout (u64 pairs, lanes = hidden index 0/1):
//  [0..4]   r: wx0, wx1, wh0, wh1, bias (prescaled 0.5; bih+bhh fused)
//  [5..9]   z: same
//  [10..12] n gi: nx0, nx1, nbi  (UNscaled)
//  [13..15] n gh: nh0, nh1, nbh  (prescaled 0.5)
__device__ __forceinline__ void gru_cell(u64 aa, u64 bb, float& h0, float& h1,
                                         const u64* __restrict__ W) {
    // x-only parts (independent of h)
    u64 xr = fma2_(W[0],  aa, fma2_(W[1],  bb, W[4]));
    u64 xz = fma2_(W[5],  aa, fma2_(W[6],  bb, W[9]));
    u64 gi = fma2_(W[10], aa, fma2_(W[11], bb, W[12]));
    // h parts (2-deep from h)
    u64 hh0 = pk(h0, h0), hh1 = pk(h1, h1);
    u64 ur = fma2_(W[2],  hh0, fma2_(W[3],  hh1, xr));
    u64 uz = fma2_(W[7],  hh0, fma2_(W[8],  hh1, xz));
    u64 gh = fma2_(W[13], hh0, fma2_(W[14], hh1, W[15]));

    float ur0, ur1, uz0, uz1;
    unpk(ur, ur0, ur1); unpk(uz, uz0, uz1);
    float tr0 = ftanh(ur0), tr1 = ftanh(ur1);
    float tz0 = ftanh(uz0), tz1 = ftanh(uz1);

    u64 s   = add2_(gi, gh);
    u64 arg = fma2_(pk(tr0, tr1), gh, s);
    float a0, a1; unpk(arg, a0, a1);

    float n0 = ftanh(a0);
    float n1 = ftanh(a1);
    float z0 = fmaf(0.5f, tz0, 0.5f);
    float z1 = fmaf(0.5f, tz1, 0.5f);
    h0 = fmaf(z0, h0 - n0, n0);
    h1 = fmaf(z1, h1 - n1, n1);
}

// smem float offsets for prepped weights
#define W_UP   0
#define W_DN   32
#define W_OBS  64
#define W_OUT  80
#define W_FLTS 84

__global__ void __launch_bounds__(TPB)
rec_policy_kernel(const float* __restrict__ x,
                  const float* __restrict__ up_wih, const float* __restrict__ up_whh,
                  const float* __restrict__ up_bih, const float* __restrict__ up_bhh,
                  const float* __restrict__ dn_wih, const float* __restrict__ dn_whh,
                  const float* __restrict__ dn_bih, const float* __restrict__ dn_bhh,
                  const float* __restrict__ obs_w, const float* __restrict__ obs_b,
                  const float* __restrict__ out_w, const float* __restrict__ out_b,
                  float* __restrict__ out, int B) {
    __shared__ __align__(16) float sw[W_FLTS];
    __shared__ __align__(16) float s[ROWS_PER_BLOCK * 19];   // input stage + hu scratch
    __shared__ __align__(16) float so[ROWS_PER_BLOCK * 7];   // output stage
    const int tid = threadIdx.x;
    const int b0  = blockIdx.x * ROWS_PER_BLOCK;
    const int nrows = min(ROWS_PER_BLOCK, B - b0);

    // ---- thread 0: compute packed+prescaled weights into smem ----
    if (tid == 0) {
#pragma unroll
        for (int g = 0; g < 2; ++g) {
            const float* wih = g ? dn_wih : up_wih;
            const float* whh = g ? dn_whh : up_whh;
            const float* bih = g ? dn_bih : up_bih;
            const float* bhh = g ? dn_bhh : up_bhh;
            float* W = sw + (g ? W_DN : W_UP);
#pragma unroll
            for (int G = 0; G < 2; ++G) {    // r (rows 0,1), z (rows 2,3)
                float* p = W + G * 10;
                p[0] = 0.5f * wih[4*G + 0]; p[1] = 0.5f * wih[4*G + 2];
                p[2] = 0.5f * wih[4*G + 1]; p[3] = 0.5f * wih[4*G + 3];
                p[4] = 0.5f * whh[4*G + 0]; p[5] = 0.5f * whh[4*G + 2];
                p[6] = 0.5f * whh[4*G + 1]; p[7] = 0.5f * whh[4*G + 3];
                p[8] = 0.5f * (bih[2*G + 0] + bhh[2*G + 0]);
                p[9] = 0.5f * (bih[2*G + 1] + bhh[2*G + 1]);
            }
            // n gate (rows 4,5): gi unscaled, gh scaled by 0.5
            W[20] = wih[8];  W[21] = wih[10];
            W[22] = wih[9];  W[23] = wih[11];
            W[24] = bih[4];  W[25] = bih[5];
            W[26] = 0.5f * whh[8]; W[27] = 0.5f * whh[10];
            W[28] = 0.5f * whh[9]; W[29] = 0.5f * whh[11];
            W[30] = 0.5f * bhh[4]; W[31] = 0.5f * bhh[5];
        }
#pragma unroll
        for (int j = 0; j < 7; ++j) {
            sw[W_OBS + 2*j + 0] = obs_w[j];
            sw[W_OBS + 2*j + 1] = obs_w[7 + j];
        }
        sw[W_OBS + 14] = obs_b[0];
        sw[W_OBS + 15] = obs_b[1];
        sw[W_OUT + 0] = out_w[0];
        sw[W_OUT + 1] = out_w[1];
        sw[W_OUT + 2] = out_b[0];
        sw[W_OUT + 3] = 0.0f;
    }

    // ---- stage input [nrows x 19] coalesced ----
    if (nrows == ROWS_PER_BLOCK) {
        const float4* src = (const float4*)(x + (size_t)b0 * 19);
        float4* dst = (float4*)s;
        constexpr int N4 = ROWS_PER_BLOCK * 19 / 4;   // 1216
#pragma unroll
        for (int i = 0; i < (N4 + TPB - 1) / TPB; ++i) {
            int idx = tid + i * TPB;
            if (idx < N4) dst[idx] = src[idx];
        }
    } else {
        for (int idx = tid; idx < nrows * 19; idx += TPB)
            s[idx] = x[(size_t)b0 * 19 + idx];
    }
    __syncthreads();

    float* rowA = s + tid * 19;                 // 19 odd -> conflict-free
    float* rowB = s + (tid + TPB) * 19;

    {
        // ---- up GRU: two independent rows share UW regs; hu written in-place ----
        u64 UW[16];
        {
            const ulonglong2* p = (const ulonglong2*)(sw + W_UP);
#pragma unroll
            for (int i = 0; i < 8; ++i) { ulonglong2 v = p[i]; UW[2*i] = v.x; UW[2*i+1] = v.y; }
        }
        float hA0 = 0.0f, hA1 = 0.0f, hB0 = 0.0f, hB1 = 0.0f;
#pragma unroll
        for (int t = 0; t < NSTEP; ++t) {
            float aA = rowA[5 + t], bA = rowA[12 + t];
            float aB = rowB[5 + t], bB = rowB[12 + t];
            gru_cell(pk(aA, aA), pk(bA, bA), hA0, hA1, UW);
            gru_cell(pk(aB, aB), pk(bB, bB), hB0, hB1, UW);
            rowA[5 + t] = hA0; rowA[12 + t] = hA1;     // hu stored in-place
            rowB[5 + t] = hB0; rowB[12 + t] = hB1;
        }

        // ---- obs linear (packed over output lanes), both rows ----
        float gA0, gA1, gB0, gB1;
        {
            u64 OW[8];
            const ulonglong2* p = (const ulonglong2*)(sw + W_OBS);
#pragma unroll
            for (int i = 0; i < 4; ++i) { ulonglong2 v = p[i]; OW[2*i] = v.x; OW[2*i+1] = v.y; }
            u64 cA = OW[7], cB = OW[7];
#pragma unroll
            for (int j = 0; j < 5; ++j) {
                float oA = rowA[j];
                float oB = rowB[j];
                cA = fma2_(OW[j], pk(oA, oA), cA);
                cB = fma2_(OW[j], pk(oB, oB), cB);
            }
            cA = fma2_(OW[5], pk(hA0, hA0), cA);
            cA = fma2_(OW[6], pk(hA1, hA1), cA);
            cB = fma2_(OW[5], pk(hB0, hB0), cB);
            cB = fma2_(OW[6], pk(hB1, hB1), cB);
            unpk(cA, gA0, gA1);
            unpk(cB, gB0, gB1);
        }

        // ---- down GRU + per-step output, both rows share DW regs ----
        u64 DW[16];
        {
            const ulonglong2* p = (const ulonglong2*)(sw + W_DN);
#pragma unroll
            for (int i = 0; i < 8; ++i) { ulonglong2 v = p[i]; DW[2*i] = v.x; DW[2*i+1] = v.y; }
        }
        const float4 wo = *(const float4*)(sw + W_OUT);
        float* orowA = so + tid * 7;            // 7 odd -> conflict-free
        float* orowB = so + (tid + TPB) * 7;
#pragma unroll
        for (int t = 0; t < NSTEP; ++t) {
            float huA0 = rowA[5 + t], huA1 = rowA[12 + t];
            float huB0 = rowB[5 + t], huB1 = rowB[12 + t];
            gru_cell(pk(huA0, huA0), pk(huA1, huA1), gA0, gA1, DW);
            gru_cell(pk(huB0, huB0), pk(huB1, huB1), gB0, gB1, DW);
            orowA[t] = fmaf(wo.x, gA0, fmaf(wo.y, gA1, wo.z));
            orowB[t] = fmaf(wo.x, gB0, fmaf(wo.y, gB1, wo.z));
        }
    }

    __syncthreads();

    // ---- stage output [nrows x 7] coalesced ----
    if (nrows == ROWS_PER_BLOCK) {
        float4* od = (float4*)(out + (size_t)b0 * 7);
        const float4* ss = (const float4*)so;
        constexpr int N4 = ROWS_PER_BLOCK * 7 / 4;  // 448
#pragma unroll
        for (int i = 0; i < (N4 + TPB - 1) / TPB; ++i) {
            int idx = tid + i * TPB;
            if (idx < N4) od[idx] = ss[idx];
        }
    } else {
        for (int idx = tid; idx < nrows * 7; idx += TPB)
            out[(size_t)b0 * 7 + idx] = so[idx];
    }
}

extern "C" void kernel_launch(void* const* d_in, const int* in_sizes, int n_in,
                              void* d_out, int out_size) {
    const float* x      = (const float*)d_in[0];
    const float* up_wih = (const float*)d_in[1];
    const float* up_whh = (const float*)d_in[2];
    const float* up_bih = (const float*)d_in[3];
    const float* up_bhh = (const float*)d_in[4];
    const float* dn_wih = (const float*)d_in[5];
    const float* dn_whh = (const float*)d_in[6];
    const float* dn_bih = (const float*)d_in[7];
    const float* dn_bhh = (const float*)d_in[8];
    const float* obs_w  = (const float*)d_in[9];
    const float* obs_b  = (const float*)d_in[10];
    const float* out_w  = (const float*)d_in[11];
    const float* out_b  = (const float*)d_in[12];
    float* out = (float*)d_out;

    const int B = in_sizes[0] / 19;
    const int grid = (B + ROWS_PER_BLOCK - 1) / ROWS_PER_BLOCK;
    rec_policy_kernel<<<grid, TPB>>>(x,
                                     up_wih, up_whh, up_bih, up_bhh,
                                     dn_wih, dn_whh, dn_bih, dn_bhh,
                                     obs_w, obs_b, out_w, out_b,
                                     out, B);
}